// round 10
// baseline (speedup 1.0000x reference)
#include <cuda_runtime.h>
#include <cuda_bf16.h>
#include <cstdint>

// B=8, SEQ=4096, DIM=64.
// out = scale * rope(Q) @ (rope(K)^T @ rope(V))   (associativity; no softmax)
// scale = 1/sqrt(64) = 0.125
// Tensor-core path: mma.sync.m16n8k8 TF32, 2-way operand split (3 MMAs).

#define BATCH  8
#define SEQ    4096
#define DIM    64
#define NC     64          // 64-row chunks per batch
#define CH     64          // rows per CTA
#define SROWS  32          // rows per stage (2 stages)

__device__ float g_partials[NC * BATCH * DIM * DIM];  // 8 MB
__device__ float g_M[BATCH * DIM * DIM];              // 128 KB

// ---------------------------------------------------------------------------
__device__ __forceinline__ uint32_t f2tf32(float x) {
    uint32_t r; asm("cvt.rna.tf32.f32 %0, %1;" : "=r"(r) : "f"(x)); return r;
}
__device__ __forceinline__ float4 rope4(float4 x, float4 f) {
    float4 o;
    o.x = x.x * f.x - x.y * f.y;  o.y = x.x * f.y + x.y * f.x;
    o.z = x.z * f.z - x.w * f.w;  o.w = x.z * f.w + x.w * f.z;
    return o;
}
__device__ __forceinline__ void mma8(float* c, const uint32_t* a, const uint32_t* b) {
    asm volatile(
        "mma.sync.aligned.m16n8k8.row.col.f32.tf32.tf32.f32 "
        "{%0,%1,%2,%3}, {%4,%5,%6,%7}, {%8,%9}, {%0,%1,%2,%3};\n"
        : "+f"(c[0]), "+f"(c[1]), "+f"(c[2]), "+f"(c[3])
        : "r"(a[0]), "r"(a[1]), "r"(a[2]), "r"(a[3]), "r"(b[0]), "r"(b[1]));
}
__device__ __forceinline__ void split1(float x, uint32_t& hi, uint32_t& lo) {
    hi = f2tf32(x);
    lo = __float_as_uint(x - __uint_as_float(hi));
}
__device__ __forceinline__ void split4(float4 v, float4& h, float4& l) {
    uint32_t h0, l0, h1, l1, h2, l2, h3, l3;
    split1(v.x, h0, l0); split1(v.y, h1, l1);
    split1(v.z, h2, l2); split1(v.w, h3, l3);
    h = make_float4(__uint_as_float(h0), __uint_as_float(h1),
                    __uint_as_float(h2), __uint_as_float(h3));
    l = make_float4(__uint_as_float(l0), __uint_as_float(l1),
                    __uint_as_float(l2), __uint_as_float(l3));
}

// ---------------------------------------------------------------------------
// k1 MMA for one 32-row stage (16 rows for this warp's k-half).
// ---------------------------------------------------------------------------
__device__ __forceinline__ void k1_mma_stage(
    float acc[8][4], const float* sk, const float* svh, const float* svl,
    int kh, int m0, int g, int tig)
{
#pragma unroll
    for (int ks = 0; ks < 2; ks++) {
        const int krow = kh * 16 + ks * 8;
        uint32_t ah[4], al[4];
        {
            const float a0 = sk[(krow + tig)     * 72 + m0 + g];
            const float a1 = sk[(krow + tig)     * 72 + m0 + g + 8];
            const float a2 = sk[(krow + tig + 4) * 72 + m0 + g];
            const float a3 = sk[(krow + tig + 4) * 72 + m0 + g + 8];
            split1(a0, ah[0], al[0]); split1(a1, ah[1], al[1]);
            split1(a2, ah[2], al[2]); split1(a3, ah[3], al[3]);
        }
#pragma unroll
        for (int j = 0; j < 8; j++) {
            const int n0 = 8 * j;
            uint32_t bh[2], bl[2];
            bh[0] = __float_as_uint(svh[(krow + tig)     * 72 + n0 + g]);
            bh[1] = __float_as_uint(svh[(krow + tig + 4) * 72 + n0 + g]);
            bl[0] = __float_as_uint(svl[(krow + tig)     * 72 + n0 + g]);
            bl[1] = __float_as_uint(svl[(krow + tig + 4) * 72 + n0 + g]);
            mma8(acc[j], ah, bh);
            mma8(acc[j], ah, bl);
            mma8(acc[j], al, bh);
        }
    }
}

// ---------------------------------------------------------------------------
// Kernel 1: partial M = rope(K)^T @ rope(V) over a 64-row chunk, 2 stages.
// 8 warps: m-tile (w&3) x k-half (w>>2). Stage 1 is register-prefetched
// during stage 0's MMA.
// ---------------------------------------------------------------------------
__global__ __launch_bounds__(256) void kv_outer_kernel(
    const float* __restrict__ K, const float* __restrict__ V,
    const float* __restrict__ FK, const float* __restrict__ FV)
{
    const int b = blockIdx.y;
    const int c = blockIdx.x;
    const int t = threadIdx.x;
    const int w = t >> 5;
    const int lane = t & 31;
    const int g = lane >> 2;
    const int tig = lane & 3;

    __shared__ float smem[3 * SROWS * 72];   // 27.6 KB
    float* sk  = smem;
    float* svh = smem + SROWS * 72;
    float* svl = smem + 2 * SROWS * 72;

    const float4* K4  = (const float4*)(K + (size_t)b * SEQ * DIM);
    const float4* V4  = (const float4*)(V + (size_t)b * SEQ * DIM);
    const float4* FK4 = (const float4*)FK;
    const float4* FV4 = (const float4*)FV;

    const int m0 = 16 * (w & 3);
    const int kh = w >> 2;
    const int r  = (t + 0) >> 4;       // staging row for u=0
    const int c4 = t & 15;

    float acc[8][4];
#pragma unroll
    for (int j = 0; j < 8; j++)
#pragma unroll
        for (int p = 0; p < 4; p++) acc[j][p] = 0.0f;

    // ---- stage 0: load + rope(+split V) + store ----
#pragma unroll
    for (int u = 0; u < 2; u++) {
        const int f  = t + 256 * u;
        const int rr = f >> 4, cc = f & 15;
        const int gi = (c * CH + rr) * 16 + cc;
        *(float4*)&sk[rr * 72 + 4 * cc] = rope4(K4[gi], FK4[gi]);
        float4 vh, vl;
        split4(rope4(V4[gi], FV4[gi]), vh, vl);
        *(float4*)&svh[rr * 72 + 4 * cc] = vh;
        *(float4*)&svl[rr * 72 + 4 * cc] = vl;
    }
    __syncthreads();

    // ---- prefetch stage 1 into registers ----
    float4 pk[2], pv[2], pfk[2], pfv[2];
#pragma unroll
    for (int u = 0; u < 2; u++) {
        const int f  = t + 256 * u;
        const int rr = f >> 4, cc = f & 15;
        const int gi = (c * CH + SROWS + rr) * 16 + cc;
        pk[u] = K4[gi]; pv[u] = V4[gi]; pfk[u] = FK4[gi]; pfv[u] = FV4[gi];
    }

    // ---- MMA stage 0 ----
    k1_mma_stage(acc, sk, svh, svl, kh, m0, g, tig);
    __syncthreads();   // all reads of stage 0 done before overwrite

    // ---- store stage 1 from prefetched regs ----
#pragma unroll
    for (int u = 0; u < 2; u++) {
        const int f  = t + 256 * u;
        const int rr = f >> 4, cc = f & 15;
        *(float4*)&sk[rr * 72 + 4 * cc] = rope4(pk[u], pfk[u]);
        float4 vh, vl;
        split4(rope4(pv[u], pfv[u]), vh, vl);
        *(float4*)&svh[rr * 72 + 4 * cc] = vh;
        *(float4*)&svl[rr * 72 + 4 * cc] = vl;
    }
    __syncthreads();

    // ---- MMA stage 1 ----
    k1_mma_stage(acc, sk, svh, svl, kh, m0, g, tig);

    // ---- combine k-halves via smem; warps 0-3 write the partial ----
    __syncthreads();
    float* comb = smem;   // 64 x 68 = 4352 floats < 6912 available
    if (w >= 4) {
#pragma unroll
        for (int j = 0; j < 8; j++) {
            const int col = 8 * j + 2 * tig;
            *(float2*)&comb[(m0 + g)     * 68 + col] = make_float2(acc[j][0], acc[j][1]);
            *(float2*)&comb[(m0 + g + 8) * 68 + col] = make_float2(acc[j][2], acc[j][3]);
        }
    }
    __syncthreads();
    if (w < 4) {
        float* P = g_partials + ((size_t)c * BATCH + b) * (DIM * DIM);
#pragma unroll
        for (int j = 0; j < 8; j++) {
            const int col = 8 * j + 2 * tig;
            const float2 u0 = *(const float2*)&comb[(m0 + g)     * 68 + col];
            const float2 u1 = *(const float2*)&comb[(m0 + g + 8) * 68 + col];
            *(float2*)&P[(m0 + g)     * DIM + col] =
                make_float2(acc[j][0] + u0.x, acc[j][1] + u0.y);
            *(float2*)&P[(m0 + g + 8) * DIM + col] =
                make_float2(acc[j][2] + u1.x, acc[j][3] + u1.y);
        }
    }
    (void)r; (void)c4;
}

// ---------------------------------------------------------------------------
// Kernel 2: reduce NC=64 partials -> g_M (8192 float4 outputs)
// ---------------------------------------------------------------------------
__global__ __launch_bounds__(256) void reduce_kernel()
{
    const int idx = blockIdx.x * 256 + threadIdx.x;
    const float4* P = (const float4*)g_partials;
    float4 s0 = make_float4(0.f, 0.f, 0.f, 0.f);
    float4 s1 = make_float4(0.f, 0.f, 0.f, 0.f);
    float4 s2 = make_float4(0.f, 0.f, 0.f, 0.f);
    float4 s3 = make_float4(0.f, 0.f, 0.f, 0.f);
#pragma unroll 4
    for (int c = 0; c < NC; c += 4) {
        const float4 a = P[(size_t)(c + 0) * 8192 + idx];
        const float4 b = P[(size_t)(c + 1) * 8192 + idx];
        const float4 d = P[(size_t)(c + 2) * 8192 + idx];
        const float4 e = P[(size_t)(c + 3) * 8192 + idx];
        s0.x += a.x; s0.y += a.y; s0.z += a.z; s0.w += a.w;
        s1.x += b.x; s1.y += b.y; s1.z += b.z; s1.w += b.w;
        s2.x += d.x; s2.y += d.y; s2.z += d.z; s2.w += d.w;
        s3.x += e.x; s3.y += e.y; s3.z += e.z; s3.w += e.w;
    }
    ((float4*)g_M)[idx] = make_float4(s0.x + s1.x + s2.x + s3.x,
                                      s0.y + s1.y + s2.y + s3.y,
                                      s0.z + s1.z + s2.z + s3.z,
                                      s0.w + s1.w + s2.w + s3.w);
}

// ---------------------------------------------------------------------------
// Kernel 3: out = scale * rope(Q) @ M[b].  64 rows per CTA, 2 stages,
// double-buffered q staging + register prefetch. 8 warps:
// m-tile (w&1 within 32-row stage) x n-quarter (w>>1).
// ---------------------------------------------------------------------------
__global__ __launch_bounds__(256) void qm_kernel(
    const float* __restrict__ Q, const float* __restrict__ FQ,
    float* __restrict__ OUT)
{
    const int b  = blockIdx.y;
    const int rc = blockIdx.x;
    const int t  = threadIdx.x;
    const int w  = t >> 5;
    const int lane = t & 31;
    const int g = lane >> 2;
    const int tig = lane & 3;

    __shared__ float sMh[DIM * 72];        // 18.4 KB
    __shared__ float sMl[DIM * 72];
    __shared__ float sq[2][SROWS * 68];    // 8.7 KB each

    // ---- load + split M[b] ----
    {
        const float4* M4 = (const float4*)(g_M + (size_t)b * DIM * DIM);
#pragma unroll
        for (int u = 0; u < 4; u++) {
            const int f  = t + 256 * u;
            const int k  = f >> 4;
            const int n0 = 4 * (f & 15);
            float4 h, l;
            split4(M4[f], h, l);
            *(float4*)&sMh[k * 72 + n0] = h;
            *(float4*)&sMl[k * 72 + n0] = l;
        }
    }

    const float4* Q4  = (const float4*)(Q + (size_t)b * SEQ * DIM);
    const float4* FQ4 = (const float4*)FQ;
    const int m0s = 16 * (w & 1);
    const int nq  = w >> 1;
    const float scale = 0.125f;

    // ---- stage 0: load + rope + store buf0 ----
#pragma unroll
    for (int u = 0; u < 2; u++) {
        const int f  = t + 256 * u;
        const int rr = f >> 4, cc = f & 15;
        const int gi = (rc * CH + rr) * 16 + cc;
        *(float4*)&sq[0][rr * 68 + 4 * cc] = rope4(Q4[gi], FQ4[gi]);
    }
    __syncthreads();   // covers M staging too

    // ---- prefetch stage 1 ----
    float4 pq[2], pf[2];
#pragma unroll
    for (int u = 0; u < 2; u++) {
        const int f  = t + 256 * u;
        const int rr = f >> 4, cc = f & 15;
        const int gi = (rc * CH + SROWS + rr) * 16 + cc;
        pq[u] = Q4[gi]; pf[u] = FQ4[gi];
    }

#pragma unroll
    for (int s = 0; s < 2; s++) {
        const int R = rc * CH + s * SROWS;
        const float* sqb = sq[s];

        float cc2[2][4];
#pragma unroll
        for (int jj = 0; jj < 2; jj++)
#pragma unroll
            for (int p = 0; p < 4; p++) cc2[jj][p] = 0.0f;

#pragma unroll
        for (int ks = 0; ks < 8; ks++) {
            const int k0 = 8 * ks;
            uint32_t ah[4], al[4];
            {
                const float a0 = sqb[(m0s + g)     * 68 + k0 + tig];
                const float a1 = sqb[(m0s + g + 8) * 68 + k0 + tig];
                const float a2 = sqb[(m0s + g)     * 68 + k0 + tig + 4];
                const float a3 = sqb[(m0s + g + 8) * 68 + k0 + tig + 4];
                split1(a0, ah[0], al[0]); split1(a1, ah[1], al[1]);
                split1(a2, ah[2], al[2]); split1(a3, ah[3], al[3]);
            }
#pragma unroll
            for (int jj = 0; jj < 2; jj++) {
                const int n0 = 8 * (2 * nq + jj);
                uint32_t bh[2], bl[2];
                bh[0] = __float_as_uint(sMh[(k0 + tig)     * 72 + n0 + g]);
                bh[1] = __float_as_uint(sMh[(k0 + tig + 4) * 72 + n0 + g]);
                bl[0] = __float_as_uint(sMl[(k0 + tig)     * 72 + n0 + g]);
                bl[1] = __float_as_uint(sMl[(k0 + tig + 4) * 72 + n0 + g]);
                mma8(cc2[jj], ah, bh);
                mma8(cc2[jj], ah, bl);
                mma8(cc2[jj], al, bh);
            }
        }

        // write this stage's 32 output rows
        float* O = OUT + ((size_t)b * SEQ + R) * DIM;
#pragma unroll
        for (int jj = 0; jj < 2; jj++) {
            const int col = 8 * (2 * nq + jj) + 2 * tig;
            *(float2*)&O[(size_t)(m0s + g)     * DIM + col] =
                make_float2(cc2[jj][0] * scale, cc2[jj][1] * scale);
            *(float2*)&O[(size_t)(m0s + g + 8) * DIM + col] =
                make_float2(cc2[jj][2] * scale, cc2[jj][3] * scale);
        }

        // stage 1 goes into buffer 1 (disjoint from buf0 being read)
        if (s == 0) {
#pragma unroll
            for (int u = 0; u < 2; u++) {
                const int f  = t + 256 * u;
                const int rr = f >> 4, cc = f & 15;
                *(float4*)&sq[1][rr * 68 + 4 * cc] = rope4(pq[u], pf[u]);
            }
            __syncthreads();
        }
    }
}

// ---------------------------------------------------------------------------
extern "C" void kernel_launch(void* const* d_in, const int* in_sizes, int n_in,
                              void* d_out, int out_size)
{
    const float* q  = (const float*)d_in[0];
    const float* k  = (const float*)d_in[1];
    const float* v  = (const float*)d_in[2];
    const float* fq = (const float*)d_in[3];
    const float* fk = (const float*)d_in[4];
    const float* fv = (const float*)d_in[5];
    float* out = (float*)d_out;

    kv_outer_kernel<<<dim3(NC, BATCH), 256>>>(k, v, fk, fv);
    reduce_kernel<<<32, 256>>>();
    qm_kernel<<<dim3(NC, BATCH), 256>>>(q, fq, out);
}

// round 11
// speedup vs baseline: 1.1367x; 1.1367x over previous
#include <cuda_runtime.h>
#include <cuda_bf16.h>
#include <cstdint>

// B=8, SEQ=4096, DIM=64.
// out = scale * rope(Q) @ (rope(K)^T @ rope(V))   (associativity; no softmax)
// scale = 1/sqrt(64) = 0.125
// Tensor path: mma.sync.m16n8k8 TF32, 2-way split (3 MMAs) for fp32 accuracy.

#define BATCH  8
#define SEQ    4096
#define DIM    64
#define NC     64          // chunks per batch (k1 and k3)
#define CH     64          // rows per CTA
#define NGRP   8           // k2 tree fan-in groups (NC/NGRP chunks each)

__device__ float g_partials[NC * BATCH * DIM * DIM];   // 8 MB
__device__ float g_p2[NGRP * BATCH * DIM * DIM];       // 1 MB
__device__ float g_M[BATCH * DIM * DIM];               // 128 KB

// ---------------------------------------------------------------------------
__device__ __forceinline__ uint32_t f2tf32(float x) {
    uint32_t r; asm("cvt.rna.tf32.f32 %0, %1;" : "=r"(r) : "f"(x)); return r;
}
__device__ __forceinline__ float4 rope4(float4 x, float4 f) {
    float4 o;
    o.x = x.x * f.x - x.y * f.y;  o.y = x.x * f.y + x.y * f.x;
    o.z = x.z * f.z - x.w * f.w;  o.w = x.z * f.w + x.w * f.z;
    return o;
}
__device__ __forceinline__ void mma8(float* c, const uint32_t* a, const uint32_t* b) {
    asm volatile(
        "mma.sync.aligned.m16n8k8.row.col.f32.tf32.tf32.f32 "
        "{%0,%1,%2,%3}, {%4,%5,%6,%7}, {%8,%9}, {%0,%1,%2,%3};\n"
        : "+f"(c[0]), "+f"(c[1]), "+f"(c[2]), "+f"(c[3])
        : "r"(a[0]), "r"(a[1]), "r"(a[2]), "r"(a[3]), "r"(b[0]), "r"(b[1]));
}
__device__ __forceinline__ void split1(float x, uint32_t& hi, uint32_t& lo) {
    hi = f2tf32(x);
    lo = __float_as_uint(x - __uint_as_float(hi));
}

// ---------------------------------------------------------------------------
// Kernel 1: partial M = rope(K)^T @ rope(V) over a 64-row chunk, ONE stage.
// 512 CTAs x 256 thr. 8 warps: m-tile (w&3) x k-half (w>>2, 32 rows, 4 ks).
// K and V staged RAW (stride 72); both split at fragment load.
// Fragment LDS word%32 = 8*tig + g (+c) -> full bank permutation, conflict-free.
// ---------------------------------------------------------------------------
__global__ __launch_bounds__(256) void kv_outer_kernel(
    const float* __restrict__ K, const float* __restrict__ V,
    const float* __restrict__ FK, const float* __restrict__ FV)
{
    const int b = blockIdx.y;
    const int c = blockIdx.x;
    const int t = threadIdx.x;
    const int w = t >> 5;
    const int lane = t & 31;
    const int g = lane >> 2;
    const int tig = lane & 3;

    __shared__ float sk[CH * 72];   // 18.4 KB
    __shared__ float sv[CH * 72];   // 18.4 KB

    const float4* K4  = (const float4*)(K + (size_t)b * SEQ * DIM);
    const float4* V4  = (const float4*)(V + (size_t)b * SEQ * DIM);
    const float4* FK4 = (const float4*)FK;
    const float4* FV4 = (const float4*)FV;

    // stage 64 rows (1024 float4 per tensor, 4 per thread), rope fused
#pragma unroll
    for (int u = 0; u < 4; u++) {
        const int f  = t + 256 * u;
        const int rr = f >> 4, cc = f & 15;
        const int gi = (c * CH + rr) * 16 + cc;
        *(float4*)&sk[rr * 72 + 4 * cc] = rope4(K4[gi], FK4[gi]);
        *(float4*)&sv[rr * 72 + 4 * cc] = rope4(V4[gi], FV4[gi]);
    }
    __syncthreads();

    const int m0 = 16 * (w & 3);
    const int kh = w >> 2;

    float acc[8][4];
#pragma unroll
    for (int j = 0; j < 8; j++)
#pragma unroll
        for (int p = 0; p < 4; p++) acc[j][p] = 0.0f;

#pragma unroll
    for (int ks = 0; ks < 4; ks++) {
        const int krow = kh * 32 + ks * 8;
        uint32_t ah[4], al[4];
        {
            const float a0 = sk[(krow + tig)     * 72 + m0 + g];
            const float a1 = sk[(krow + tig)     * 72 + m0 + g + 8];
            const float a2 = sk[(krow + tig + 4) * 72 + m0 + g];
            const float a3 = sk[(krow + tig + 4) * 72 + m0 + g + 8];
            split1(a0, ah[0], al[0]); split1(a1, ah[1], al[1]);
            split1(a2, ah[2], al[2]); split1(a3, ah[3], al[3]);
        }
#pragma unroll
        for (int j = 0; j < 8; j++) {
            const int n0 = 8 * j;
            const float r0 = sv[(krow + tig)     * 72 + n0 + g];
            const float r1 = sv[(krow + tig + 4) * 72 + n0 + g];
            uint32_t bh[2], bl[2];
            split1(r0, bh[0], bl[0]);
            split1(r1, bh[1], bl[1]);
            mma8(acc[j], ah, bh);
            mma8(acc[j], ah, bl);
            mma8(acc[j], al, bh);
        }
    }

    // combine k-halves via smem (reuse sk: 64*68=4352 <= 4608), write partial
    __syncthreads();
    float* comb = sk;
    if (w >= 4) {
#pragma unroll
        for (int j = 0; j < 8; j++) {
            const int col = 8 * j + 2 * tig;
            *(float2*)&comb[(m0 + g)     * 68 + col] = make_float2(acc[j][0], acc[j][1]);
            *(float2*)&comb[(m0 + g + 8) * 68 + col] = make_float2(acc[j][2], acc[j][3]);
        }
    }
    __syncthreads();
    if (w < 4) {
        float* P = g_partials + ((size_t)c * BATCH + b) * (DIM * DIM);
#pragma unroll
        for (int j = 0; j < 8; j++) {
            const int col = 8 * j + 2 * tig;
            const float2 u0 = *(const float2*)&comb[(m0 + g)     * 68 + col];
            const float2 u1 = *(const float2*)&comb[(m0 + g + 8) * 68 + col];
            *(float2*)&P[(m0 + g)     * DIM + col] =
                make_float2(acc[j][0] + u0.x, acc[j][1] + u0.y);
            *(float2*)&P[(m0 + g + 8) * DIM + col] =
                make_float2(acc[j][2] + u1.x, acc[j][3] + u1.y);
        }
    }
}

// ---------------------------------------------------------------------------
// Kernel 2a: tree reduce level 1. 65536 threads; thread (grp, o) sums
// chunks grp*8..grp*8+7 of float4 column o. Full-MLP, BW-bound.
// ---------------------------------------------------------------------------
__global__ __launch_bounds__(256) void reduce_a_kernel()
{
    const int idx = blockIdx.x * 256 + threadIdx.x;   // 0..65535
    const int grp = idx >> 13;                        // 0..7
    const int o   = idx & 8191;                       // float4 column
    const float4* P = (const float4*)g_partials;
    float4 s0 = make_float4(0.f, 0.f, 0.f, 0.f);
    float4 s1 = make_float4(0.f, 0.f, 0.f, 0.f);
#pragma unroll
    for (int i = 0; i < 8; i += 2) {
        const float4 a = P[(size_t)(grp * 8 + i)     * 8192 + o];
        const float4 e = P[(size_t)(grp * 8 + i + 1) * 8192 + o];
        s0.x += a.x; s0.y += a.y; s0.z += a.z; s0.w += a.w;
        s1.x += e.x; s1.y += e.y; s1.z += e.z; s1.w += e.w;
    }
    ((float4*)g_p2)[(size_t)grp * 8192 + o] =
        make_float4(s0.x + s1.x, s0.y + s1.y, s0.z + s1.z, s0.w + s1.w);
}

// ---------------------------------------------------------------------------
// Kernel 2b: tree reduce level 2 (1 MB, L2-hot). 8192 threads.
// ---------------------------------------------------------------------------
__global__ __launch_bounds__(256) void reduce_b_kernel()
{
    const int o = blockIdx.x * 256 + threadIdx.x;     // 0..8191
    const float4* P = (const float4*)g_p2;
    float4 s0 = make_float4(0.f, 0.f, 0.f, 0.f);
    float4 s1 = make_float4(0.f, 0.f, 0.f, 0.f);
#pragma unroll
    for (int i = 0; i < NGRP; i += 2) {
        const float4 a = P[(size_t)i       * 8192 + o];
        const float4 e = P[(size_t)(i + 1) * 8192 + o];
        s0.x += a.x; s0.y += a.y; s0.z += a.z; s0.w += a.w;
        s1.x += e.x; s1.y += e.y; s1.z += e.z; s1.w += e.w;
    }
    ((float4*)g_M)[o] = make_float4(s0.x + s1.x, s0.y + s1.y,
                                    s0.z + s1.z, s0.w + s1.w);
}

// ---------------------------------------------------------------------------
// Kernel 3: out = scale * rope(Q) @ M[b].  512 CTAs x 256 thr, 64 rows each.
// M fragments REGISTER-RESIDENT per warp (loaded once from L2-hot g_M,
// split in regs) -> no smem M staging, no staging sync. q double-buffered.
// 8 warps: m-tile (w&1 within 32-row stage) x n-quarter (w>>1).
// ---------------------------------------------------------------------------
__global__ __launch_bounds__(256) void qm_kernel(
    const float* __restrict__ Q, const float* __restrict__ FQ,
    float* __restrict__ OUT)
{
    const int b  = blockIdx.y;
    const int rc = blockIdx.x;
    const int t  = threadIdx.x;
    const int w  = t >> 5;
    const int lane = t & 31;
    const int g = lane >> 2;
    const int tig = lane & 3;

    __shared__ float sq[2][32 * 68];   // 8.7 KB each

    const int m0s = 16 * (w & 1);
    const int nq  = w >> 1;

    // ---- M fragments -> registers (one-time, L2-hot) ----
    uint32_t Bh[8][2][2], Bl[8][2][2];
    {
        const float* Mb = g_M + (size_t)b * DIM * DIM;
#pragma unroll
        for (int ks = 0; ks < 8; ks++) {
            const int k0 = 8 * ks;
#pragma unroll
            for (int jj = 0; jj < 2; jj++) {
                const int n0 = 8 * (2 * nq + jj);
                const float r0 = Mb[(k0 + tig)     * DIM + n0 + g];
                const float r1 = Mb[(k0 + tig + 4) * DIM + n0 + g];
                split1(r0, Bh[ks][jj][0], Bl[ks][jj][0]);
                split1(r1, Bh[ks][jj][1], Bl[ks][jj][1]);
            }
        }
    }

    const float4* Q4  = (const float4*)(Q + (size_t)b * SEQ * DIM);
    const float4* FQ4 = (const float4*)FQ;
    const float scale = 0.125f;

    // ---- stage 0: rope 32 q rows into buf0 ----
#pragma unroll
    for (int u = 0; u < 2; u++) {
        const int f  = t + 256 * u;
        const int rr = f >> 4, cc = f & 15;
        const int gi = (rc * CH + rr) * 16 + cc;
        *(float4*)&sq[0][rr * 68 + 4 * cc] = rope4(Q4[gi], FQ4[gi]);
    }
    __syncthreads();

    // ---- prefetch stage 1 ----
    float4 pq[2], pf[2];
#pragma unroll
    for (int u = 0; u < 2; u++) {
        const int f  = t + 256 * u;
        const int rr = f >> 4, cc = f & 15;
        const int gi = (rc * CH + 32 + rr) * 16 + cc;
        pq[u] = Q4[gi]; pf[u] = FQ4[gi];
    }

#pragma unroll
    for (int s = 0; s < 2; s++) {
        const float* sqb = sq[s];
        float cc2[2][4];
#pragma unroll
        for (int jj = 0; jj < 2; jj++)
#pragma unroll
            for (int p = 0; p < 4; p++) cc2[jj][p] = 0.0f;

#pragma unroll
        for (int ks = 0; ks < 8; ks++) {
            const int k0 = 8 * ks;
            uint32_t ah[4], al[4];
            {
                const float a0 = sqb[(m0s + g)     * 68 + k0 + tig];
                const float a1 = sqb[(m0s + g + 8) * 68 + k0 + tig];
                const float a2 = sqb[(m0s + g)     * 68 + k0 + tig + 4];
                const float a3 = sqb[(m0s + g + 8) * 68 + k0 + tig + 4];
                split1(a0, ah[0], al[0]); split1(a1, ah[1], al[1]);
                split1(a2, ah[2], al[2]); split1(a3, ah[3], al[3]);
            }
#pragma unroll
            for (int jj = 0; jj < 2; jj++) {
                mma8(cc2[jj], ah, Bh[ks][jj]);
                mma8(cc2[jj], ah, Bl[ks][jj]);
                mma8(cc2[jj], al, Bh[ks][jj]);
            }
        }

        // write this stage's rows
        float* O = OUT + ((size_t)b * SEQ + rc * CH + s * 32) * DIM;
#pragma unroll
        for (int jj = 0; jj < 2; jj++) {
            const int col = 8 * (2 * nq + jj) + 2 * tig;
            *(float2*)&O[(size_t)(m0s + g)     * DIM + col] =
                make_float2(cc2[jj][0] * scale, cc2[jj][1] * scale);
            *(float2*)&O[(size_t)(m0s + g + 8) * DIM + col] =
                make_float2(cc2[jj][2] * scale, cc2[jj][3] * scale);
        }

        if (s == 0) {
#pragma unroll
            for (int u = 0; u < 2; u++) {
                const int f  = t + 256 * u;
                const int rr = f >> 4, cc = f & 15;
                *(float4*)&sq[1][rr * 68 + 4 * cc] = rope4(pq[u], pf[u]);
            }
            __syncthreads();
        }
    }
}

// ---------------------------------------------------------------------------
extern "C" void kernel_launch(void* const* d_in, const int* in_sizes, int n_in,
                              void* d_out, int out_size)
{
    const float* q  = (const float*)d_in[0];
    const float* k  = (const float*)d_in[1];
    const float* v  = (const float*)d_in[2];
    const float* fq = (const float*)d_in[3];
    const float* fk = (const float*)d_in[4];
    const float* fv = (const float*)d_in[5];
    float* out = (float*)d_out;

    kv_outer_kernel<<<dim3(NC, BATCH), 256>>>(k, v, fk, fv);
    reduce_a_kernel<<<256, 256>>>();
    reduce_b_kernel<<<32, 256>>>();
    qm_kernel<<<dim3(NC, BATCH), 256>>>(q, fq, out);
}

// round 12
// speedup vs baseline: 1.1380x; 1.0012x over previous
#include <cuda_runtime.h>
#include <cuda_bf16.h>
#include <cstdint>

// B=8, SEQ=4096, DIM=64.
// out = scale * rope(Q) @ (rope(K)^T @ rope(V))   (associativity; no softmax)
// scale = 1/sqrt(64) = 0.125
// Tensor path: mma.sync.m16n8k8 TF32, 2-way split (3 MMAs) for fp32 accuracy.

#define BATCH  8
#define SEQ    4096
#define DIM    64
#define NC     64          // k1 chunks per batch
#define CH     64          // k1 rows per CTA
#define NGRP   8           // k2 tree fan-in
#define CH3    128         // k3 rows per CTA
#define SROWS  32          // k3 rows per stage
#define NSTG3  (CH3 / SROWS)

__device__ float g_partials[NC * BATCH * DIM * DIM];   // 8 MB
__device__ float g_p2[NGRP * BATCH * DIM * DIM];       // 1 MB
__device__ float g_M[BATCH * DIM * DIM];               // 128 KB

// ---------------------------------------------------------------------------
__device__ __forceinline__ uint32_t f2tf32(float x) {
    uint32_t r; asm("cvt.rna.tf32.f32 %0, %1;" : "=r"(r) : "f"(x)); return r;
}
__device__ __forceinline__ float4 rope4(float4 x, float4 f) {
    float4 o;
    o.x = x.x * f.x - x.y * f.y;  o.y = x.x * f.y + x.y * f.x;
    o.z = x.z * f.z - x.w * f.w;  o.w = x.z * f.w + x.w * f.z;
    return o;
}
__device__ __forceinline__ void mma8(float* c, const uint32_t* a, const uint32_t* b) {
    asm volatile(
        "mma.sync.aligned.m16n8k8.row.col.f32.tf32.tf32.f32 "
        "{%0,%1,%2,%3}, {%4,%5,%6,%7}, {%8,%9}, {%0,%1,%2,%3};\n"
        : "+f"(c[0]), "+f"(c[1]), "+f"(c[2]), "+f"(c[3])
        : "r"(a[0]), "r"(a[1]), "r"(a[2]), "r"(a[3]), "r"(b[0]), "r"(b[1]));
}
__device__ __forceinline__ void split1(float x, uint32_t& hi, uint32_t& lo) {
    hi = f2tf32(x);
    lo = __float_as_uint(x - __uint_as_float(hi));
}
__device__ __forceinline__ void split4(float4 v, float4& h, float4& l) {
    uint32_t h0, l0, h1, l1, h2, l2, h3, l3;
    split1(v.x, h0, l0); split1(v.y, h1, l1);
    split1(v.z, h2, l2); split1(v.w, h3, l3);
    h = make_float4(__uint_as_float(h0), __uint_as_float(h1),
                    __uint_as_float(h2), __uint_as_float(h3));
    l = make_float4(__uint_as_float(l0), __uint_as_float(l1),
                    __uint_as_float(l2), __uint_as_float(l3));
}

// ---------------------------------------------------------------------------
// Kernel 1: partial M = rope(K)^T @ rope(V) over a 64-row chunk, ONE stage.
// 512 CTAs x 256 thr. 8 warps: m-tile (w&3) x k-half (w>>2, 32 rows, 4 ks).
// K and V staged RAW (stride 72); both split at fragment load.
// ---------------------------------------------------------------------------
__global__ __launch_bounds__(256) void kv_outer_kernel(
    const float* __restrict__ K, const float* __restrict__ V,
    const float* __restrict__ FK, const float* __restrict__ FV)
{
    const int b = blockIdx.y;
    const int c = blockIdx.x;
    const int t = threadIdx.x;
    const int w = t >> 5;
    const int lane = t & 31;
    const int g = lane >> 2;
    const int tig = lane & 3;

    __shared__ float sk[CH * 72];   // 18.4 KB
    __shared__ float sv[CH * 72];   // 18.4 KB

    const float4* K4  = (const float4*)(K + (size_t)b * SEQ * DIM);
    const float4* V4  = (const float4*)(V + (size_t)b * SEQ * DIM);
    const float4* FK4 = (const float4*)FK;
    const float4* FV4 = (const float4*)FV;

    // stage 64 rows (1024 float4 per tensor, 4 per thread), rope fused
#pragma unroll
    for (int u = 0; u < 4; u++) {
        const int f  = t + 256 * u;
        const int rr = f >> 4, cc = f & 15;
        const int gi = (c * CH + rr) * 16 + cc;
        *(float4*)&sk[rr * 72 + 4 * cc] = rope4(K4[gi], FK4[gi]);
        *(float4*)&sv[rr * 72 + 4 * cc] = rope4(V4[gi], FV4[gi]);
    }
    __syncthreads();

    const int m0 = 16 * (w & 3);
    const int kh = w >> 2;

    float acc[8][4];
#pragma unroll
    for (int j = 0; j < 8; j++)
#pragma unroll
        for (int p = 0; p < 4; p++) acc[j][p] = 0.0f;

#pragma unroll
    for (int ks = 0; ks < 4; ks++) {
        const int krow = kh * 32 + ks * 8;
        uint32_t ah[4], al[4];
        {
            const float a0 = sk[(krow + tig)     * 72 + m0 + g];
            const float a1 = sk[(krow + tig)     * 72 + m0 + g + 8];
            const float a2 = sk[(krow + tig + 4) * 72 + m0 + g];
            const float a3 = sk[(krow + tig + 4) * 72 + m0 + g + 8];
            split1(a0, ah[0], al[0]); split1(a1, ah[1], al[1]);
            split1(a2, ah[2], al[2]); split1(a3, ah[3], al[3]);
        }
#pragma unroll
        for (int j = 0; j < 8; j++) {
            const int n0 = 8 * j;
            const float r0 = sv[(krow + tig)     * 72 + n0 + g];
            const float r1 = sv[(krow + tig + 4) * 72 + n0 + g];
            uint32_t bh[2], bl[2];
            split1(r0, bh[0], bl[0]);
            split1(r1, bh[1], bl[1]);
            mma8(acc[j], ah, bh);
            mma8(acc[j], ah, bl);
            mma8(acc[j], al, bh);
        }
    }

    // combine k-halves via smem (reuse sk: 64*68=4352 <= 4608), write partial
    __syncthreads();
    float* comb = sk;
    if (w >= 4) {
#pragma unroll
        for (int j = 0; j < 8; j++) {
            const int col = 8 * j + 2 * tig;
            *(float2*)&comb[(m0 + g)     * 68 + col] = make_float2(acc[j][0], acc[j][1]);
            *(float2*)&comb[(m0 + g + 8) * 68 + col] = make_float2(acc[j][2], acc[j][3]);
        }
    }
    __syncthreads();
    if (w < 4) {
        float* P = g_partials + ((size_t)c * BATCH + b) * (DIM * DIM);
#pragma unroll
        for (int j = 0; j < 8; j++) {
            const int col = 8 * j + 2 * tig;
            const float2 u0 = *(const float2*)&comb[(m0 + g)     * 68 + col];
            const float2 u1 = *(const float2*)&comb[(m0 + g + 8) * 68 + col];
            *(float2*)&P[(m0 + g)     * DIM + col] =
                make_float2(acc[j][0] + u0.x, acc[j][1] + u0.y);
            *(float2*)&P[(m0 + g + 8) * DIM + col] =
                make_float2(acc[j][2] + u1.x, acc[j][3] + u1.y);
        }
    }
}

// ---------------------------------------------------------------------------
// Kernel 2a: tree reduce level 1. 65536 threads; thread (grp, o) sums
// chunks grp*8..grp*8+7 of float4 column o. Full-MLP, BW-bound.
// ---------------------------------------------------------------------------
__global__ __launch_bounds__(256) void reduce_a_kernel()
{
    const int idx = blockIdx.x * 256 + threadIdx.x;   // 0..65535
    const int grp = idx >> 13;                        // 0..7
    const int o   = idx & 8191;                       // float4 column
    const float4* P = (const float4*)g_partials;
    float4 s0 = make_float4(0.f, 0.f, 0.f, 0.f);
    float4 s1 = make_float4(0.f, 0.f, 0.f, 0.f);
#pragma unroll
    for (int i = 0; i < 8; i += 2) {
        const float4 a = P[(size_t)(grp * 8 + i)     * 8192 + o];
        const float4 e = P[(size_t)(grp * 8 + i + 1) * 8192 + o];
        s0.x += a.x; s0.y += a.y; s0.z += a.z; s0.w += a.w;
        s1.x += e.x; s1.y += e.y; s1.z += e.z; s1.w += e.w;
    }
    ((float4*)g_p2)[(size_t)grp * 8192 + o] =
        make_float4(s0.x + s1.x, s0.y + s1.y, s0.z + s1.z, s0.w + s1.w);
}

// ---------------------------------------------------------------------------
// Kernel 2b: tree reduce level 2 (1 MB, L2-hot). 8192 threads.
// ---------------------------------------------------------------------------
__global__ __launch_bounds__(256) void reduce_b_kernel()
{
    const int o = blockIdx.x * 256 + threadIdx.x;     // 0..8191
    const float4* P = (const float4*)g_p2;
    float4 s0 = make_float4(0.f, 0.f, 0.f, 0.f);
    float4 s1 = make_float4(0.f, 0.f, 0.f, 0.f);
#pragma unroll
    for (int i = 0; i < NGRP; i += 2) {
        const float4 a = P[(size_t)i       * 8192 + o];
        const float4 e = P[(size_t)(i + 1) * 8192 + o];
        s0.x += a.x; s0.y += a.y; s0.z += a.z; s0.w += a.w;
        s1.x += e.x; s1.y += e.y; s1.z += e.z; s1.w += e.w;
    }
    ((float4*)g_M)[o] = make_float4(s0.x + s1.x, s0.y + s1.y,
                                    s0.z + s1.z, s0.w + s1.w);
}

// ---------------------------------------------------------------------------
// Kernel 3: out = scale * rope(Q) @ M[b].  256 CTAs x 256 thr, 128 rows,
// 4 stages. M pre-split hi/lo in smem once per CTA (R9-verified design);
// q staged raw (stride 68), split at fragment load.
// 8 warps: m-tile (w&1: 16 of 32 staged rows) x n-quarter (w>>1).
// ---------------------------------------------------------------------------
__global__ __launch_bounds__(256) void qm_kernel(
    const float* __restrict__ Q, const float* __restrict__ FQ,
    float* __restrict__ OUT)
{
    const int b  = blockIdx.y;
    const int rc = blockIdx.x;
    const int t  = threadIdx.x;
    const int w  = t >> 5;
    const int lane = t & 31;
    const int g = lane >> 2;
    const int tig = lane & 3;

    __shared__ float smem[2 * DIM * 72 + SROWS * 68];  // 45.6 KB
    float* sMh = smem;                 // [k][n] stride 72
    float* sMl = smem + DIM * 72;
    float* sq  = smem + 2 * DIM * 72;  // [row][d] stride 68

    // ---- load + split M[b] (1024 float4, 4 per thread) ----
    {
        const float4* M4 = (const float4*)(g_M + (size_t)b * DIM * DIM);
#pragma unroll
        for (int u = 0; u < 4; u++) {
            const int f  = t + 256 * u;
            const int k  = f >> 4;
            const int n0 = 4 * (f & 15);
            float4 h, l;
            split4(M4[f], h, l);
            *(float4*)&sMh[k * 72 + n0] = h;
            *(float4*)&sMl[k * 72 + n0] = l;
        }
    }

    const float4* Q4  = (const float4*)(Q + (size_t)b * SEQ * DIM);
    const float4* FQ4 = (const float4*)FQ;
    const int m0s = 16 * (w & 1);
    const int nq  = w >> 1;           // 0..3
    const float scale = 0.125f;       // 1/sqrt(64)

#pragma unroll 1
    for (int s = 0; s < NSTG3; s++) {
        if (s) __syncthreads();       // prev stage's sq fully consumed
        const int R = rc * CH3 + s * SROWS;
        // ---- stage 32 rope'd Q rows ----
#pragma unroll
        for (int u = 0; u < 2; u++) {
            const int f  = t + 256 * u;
            const int r  = f >> 4;
            const int c4 = f & 15;
            const int gi = (R + r) * 16 + c4;
            *(float4*)&sq[r * 68 + 4 * c4] = rope4(Q4[gi], FQ4[gi]);
        }
        __syncthreads();   // also covers the one-time M staging at s=0

        float cc[2][4];
#pragma unroll
        for (int jj = 0; jj < 2; jj++)
#pragma unroll
            for (int p = 0; p < 4; p++) cc[jj][p] = 0.0f;

#pragma unroll
        for (int ks = 0; ks < 8; ks++) {
            const int k0 = 8 * ks;
            uint32_t ah[4], al[4];
            {
                const float a0 = sq[(m0s + g)     * 68 + k0 + tig];
                const float a1 = sq[(m0s + g + 8) * 68 + k0 + tig];
                const float a2 = sq[(m0s + g)     * 68 + k0 + tig + 4];
                const float a3 = sq[(m0s + g + 8) * 68 + k0 + tig + 4];
                split1(a0, ah[0], al[0]); split1(a1, ah[1], al[1]);
                split1(a2, ah[2], al[2]); split1(a3, ah[3], al[3]);
            }
#pragma unroll
            for (int jj = 0; jj < 2; jj++) {
                const int n0 = 8 * (2 * nq + jj);
                uint32_t bh[2], bl[2];
                bh[0] = __float_as_uint(sMh[(k0 + tig)     * 72 + n0 + g]);
                bh[1] = __float_as_uint(sMh[(k0 + tig + 4) * 72 + n0 + g]);
                bl[0] = __float_as_uint(sMl[(k0 + tig)     * 72 + n0 + g]);
                bl[1] = __float_as_uint(sMl[(k0 + tig + 4) * 72 + n0 + g]);
                mma8(cc[jj], ah, bh);
                mma8(cc[jj], ah, bl);
                mma8(cc[jj], al, bh);
            }
        }

        // ---- write 16 output rows for this warp's tiles ----
        float* O = OUT + ((size_t)b * SEQ + R) * DIM;
#pragma unroll
        for (int jj = 0; jj < 2; jj++) {
            const int col = 8 * (2 * nq + jj) + 2 * tig;
            *(float2*)&O[(size_t)(m0s + g)     * DIM + col] =
                make_float2(cc[jj][0] * scale, cc[jj][1] * scale);
            *(float2*)&O[(size_t)(m0s + g + 8) * DIM + col] =
                make_float2(cc[jj][2] * scale, cc[jj][3] * scale);
        }
    }
}

// ---------------------------------------------------------------------------
extern "C" void kernel_launch(void* const* d_in, const int* in_sizes, int n_in,
                              void* d_out, int out_size)
{
    const float* q  = (const float*)d_in[0];
    const float* k  = (const float*)d_in[1];
    const float* v  = (const float*)d_in[2];
    const float* fq = (const float*)d_in[3];
    const float* fk = (const float*)d_in[4];
    const float* fv = (const float*)d_in[5];
    float* out = (float*)d_out;

    kv_outer_kernel<<<dim3(NC, BATCH), 256>>>(k, v, fk, fv);
    reduce_a_kernel<<<256, 256>>>();
    reduce_b_kernel<<<32, 256>>>();
    qm_kernel<<<dim3(SEQ / CH3, BATCH), 256>>>(q, fq, out);
}